// round 17
// baseline (speedup 1.0000x reference)
#include <cuda_runtime.h>
#include <cuda_bf16.h>
#include <cuda_fp16.h>
#include <math.h>
#include <stdint.h>

#define BB   16
#define HH   256
#define LL   4096
#define DIN  100
#define DMID 512
#define DOUTP 100
#define NST  32
#define CH   64
#define NC   64
#define MTOK (BB * LL)

// ---------------- intermediates ----------------
__device__ float g_wS[HH * NST * 2];      // w^64 per (h,n)
__device__ uint16_t g_uH[BB * HH * LL];   // encoder output fp16, (B,H,L)
__device__ uint16_t g_hresH[BB * HH * LL];// post-gelu residual fp16, (B,H,L)

// ---------------- fp16 planes (GEMM path) ----------------
__device__ uint16_t g_xH[MTOK * 128];                         // x fp16, padded 100->128
__device__ uint16_t g_wencH[HH * 128];                        // enc_w fp16
__device__ uint16_t g_w1H[DMID * HH];
__device__ uint16_t g_w2H[128 * DMID];                        // dec2_w padded rows
__device__ uint16_t g_tlnH[BB * LL * HH];                     // LN out fp16
__device__ uint16_t g_zH[MTOK * DMID];                        // MLP hidden fp16

// ---------------- fp16 hi/lo split planes (S4 matrices) ----------------
__device__ uint16_t g_VSh[HH * 64 * 64], g_VSl[HH * 64 * 64];     // [h][s][t]
__device__ uint16_t g_CMSh[HH * 64 * 128], g_CMSl[HH * 64 * 128]; // [h][t][k]

__device__ __forceinline__ float gelu_f(float x) {
    return 0.5f * x * (1.0f + erff(x * 0.70710678118654752f));
}
__device__ __forceinline__ void splith(float v, uint16_t& h, uint16_t& l) {
    __half hh = __float2half_rn(v);
    __half ll = __float2half_rn(v - __half2float(hh));
    h = *(uint16_t*)&hh; l = *(uint16_t*)&ll;
}
__device__ __forceinline__ void mma16816h(float* c, const uint32_t* a, uint32_t b0, uint32_t b1) {
    asm volatile(
        "mma.sync.aligned.m16n8k16.row.col.f32.f16.f16.f32 "
        "{%0,%1,%2,%3}, {%4,%5,%6,%7}, {%8,%9}, {%0,%1,%2,%3};"
        : "+f"(c[0]), "+f"(c[1]), "+f"(c[2]), "+f"(c[3])
        : "r"(a[0]), "r"(a[1]), "r"(a[2]), "r"(a[3]), "r"(b0), "r"(b1));
}
__device__ __forceinline__ void ldsm_x4(uint32_t* r, uint32_t addr) {
    asm volatile("ldmatrix.sync.aligned.m8n8.x4.shared.b16 {%0,%1,%2,%3}, [%4];"
        : "=r"(r[0]), "=r"(r[1]), "=r"(r[2]), "=r"(r[3]) : "r"(addr));
}
__device__ __forceinline__ uint32_t smem_u32(const void* p) {
    uint32_t a;
    asm("{ .reg .u64 t; cvta.to.shared.u64 t, %1; cvt.u32.u64 %0, t; }" : "=r"(a) : "l"(p));
    return a;
}
#define CP16(dst, src) asm volatile("cp.async.cg.shared.global [%0], [%1], 16;" :: "r"(dst), "l"(src))
#define CPCOMMIT() asm volatile("cp.async.commit_group;" ::: "memory")
#define CPWAIT1() asm volatile("cp.async.wait_group 1;" ::: "memory")
#define CPWAIT0() asm volatile("cp.async.wait_group 0;" ::: "memory")

// ---------------- fp16 convert/pad kernel ----------------
__global__ void conv_pad_h(const float* __restrict__ src, uint16_t* __restrict__ d,
                           int M, int K, int Kp, int total)
{
    int i = blockIdx.x * 256 + threadIdx.x;
    if (i >= total) return;
    int r = i / Kp, c = i - r * Kp;
    float v = (r < M && c < K) ? src[(long)r * K + c] : 0.0f;
    __half hv = __float2half_rn(v);
    d[i] = *(uint16_t*)&hv;
}

// ============ pure fp16 tensor-core GEMM: C[M,N] = A[M,K]*B[N,K]^T + bias ============
#define SAST 72
#define PLANE_BYTES (128 * SAST * 2)    // 18432
#define HBUF_BYTES (2 * PLANE_BYTES)    // 36864
#define GH_SMEM (2 * HBUF_BYTES)        // 73728

// OM: 0 = fp32 out + Nvalid guard (dec2); 1 = fp16 out + gelu (dec1);
//     2 = transposed fp16 out (encoder -> g_uH (B,H,L))
template <bool GELU, int OM>
__global__ void __launch_bounds__(256, 2)
gemm_h(const uint16_t* __restrict__ A, const uint16_t* __restrict__ B,
       const float* __restrict__ bias, float* __restrict__ Cf,
       uint16_t* __restrict__ Co, int K, int Nvalid, int ldc)
{
    extern __shared__ char smem[];
    uint32_t sb = smem_u32(smem);
    int tid = threadIdx.x;
    int warp = tid >> 5, lane = tid & 31;
    int warp_m = warp >> 1, warp_n = warp & 1;
    int g = lane >> 2, tg = lane & 3;
    int m0 = blockIdx.y * 128, n0 = blockIdx.x * 128;

    uint32_t a_row = (uint32_t)(lane & 15) * (SAST * 2) + ((lane & 16) ? 16u : 0u);
    uint32_t b_row = ((uint32_t)(lane & 7) + ((lane & 16) ? 8u : 0u)) * (SAST * 2)
                   + ((lane & 8) ? 16u : 0u);

    auto load_chunk = [&](int buf, int k0) {
        uint32_t base = sb + (uint32_t)buf * HBUF_BYTES;
#pragma unroll
        for (int p = 0; p < 8; p++) {
            int idx = tid + p * 256;
            int pl = idx >> 10;
            int rem = idx & 1023;
            int row = rem >> 3, seg = rem & 7;
            uint32_t doff = (uint32_t)pl * PLANE_BYTES + (uint32_t)(row * SAST + seg * 8) * 2;
            const uint16_t* src = (pl == 0) ? (A + (long)(m0 + row) * K + k0 + seg * 8)
                                            : (B + (long)(n0 + row) * K + k0 + seg * 8);
            CP16(base + doff, src);
        }
    };

    float acc[2][8][4];
#pragma unroll
    for (int mt = 0; mt < 2; mt++)
#pragma unroll
        for (int nt = 0; nt < 8; nt++)
#pragma unroll
            for (int q = 0; q < 4; q++) acc[mt][nt][q] = 0.0f;

    int nch = K >> 6;
    load_chunk(0, 0);
    CPCOMMIT();
    for (int c = 0; c < nch; c++) {
        if (c + 1 < nch) { load_chunk((c + 1) & 1, (c + 1) << 6); CPCOMMIT(); CPWAIT1(); }
        else CPWAIT0();
        __syncthreads();
        uint32_t bufb = sb + (uint32_t)(c & 1) * HBUF_BYTES;
        uint32_t pA = bufb, pB = bufb + PLANE_BYTES;
#pragma unroll
        for (int ks = 0; ks < 4; ks++) {
            uint32_t kboff = (uint32_t)(ks * 16) * 2;
            uint32_t ah[2][4];
#pragma unroll
            for (int mt = 0; mt < 2; mt++) {
                uint32_t ro = (uint32_t)(warp_m * 32 + mt * 16) * (SAST * 2) + a_row + kboff;
                ldsm_x4(ah[mt], pA + ro);
            }
            uint32_t bA[4], bBuf[4];
            uint32_t nbase = (uint32_t)(warp_n * 64) * (SAST * 2) + b_row + kboff;
            ldsm_x4(bA, pB + nbase);
            ldsm_x4(bBuf, pB + nbase + 16 * (SAST * 2));
#pragma unroll
            for (int sub = 0; sub < 2; sub++)
#pragma unroll
                for (int mt = 0; mt < 2; mt++)
                    mma16816h(acc[mt][0 * 2 + sub], ah[mt], bA[sub * 2], bA[sub * 2 + 1]);
            ldsm_x4(bA, pB + nbase + 32 * (SAST * 2));
#pragma unroll
            for (int sub = 0; sub < 2; sub++)
#pragma unroll
                for (int mt = 0; mt < 2; mt++)
                    mma16816h(acc[mt][1 * 2 + sub], ah[mt], bBuf[sub * 2], bBuf[sub * 2 + 1]);
            ldsm_x4(bBuf, pB + nbase + 48 * (SAST * 2));
#pragma unroll
            for (int sub = 0; sub < 2; sub++)
#pragma unroll
                for (int mt = 0; mt < 2; mt++)
                    mma16816h(acc[mt][2 * 2 + sub], ah[mt], bA[sub * 2], bA[sub * 2 + 1]);
#pragma unroll
            for (int sub = 0; sub < 2; sub++)
#pragma unroll
                for (int mt = 0; mt < 2; mt++)
                    mma16816h(acc[mt][3 * 2 + sub], ah[mt], bBuf[sub * 2], bBuf[sub * 2 + 1]);
        }
        __syncthreads();
    }

    // -------- epilogue via smem stage --------
    float* stage = (float*)smem;
    for (int nh = 0; nh < 2; nh++) {
        if (warp_n == nh) {
#pragma unroll
            for (int mt = 0; mt < 2; mt++) {
#pragma unroll
                for (int nt = 0; nt < 8; nt++) {
                    int nl = nt * 8 + tg * 2;
                    int ng = n0 + nh * 64 + nl;
                    int r0 = warp_m * 32 + mt * 16 + g;
                    float b0v = (OM == 0) ? ((ng < Nvalid) ? bias[ng] : 0.0f) : bias[ng];
                    float b1v = (OM == 0) ? ((ng + 1 < Nvalid) ? bias[ng + 1] : 0.0f) : bias[ng + 1];
                    float v0 = acc[mt][nt][0] + b0v;
                    float v1 = acc[mt][nt][1] + b1v;
                    float v2 = acc[mt][nt][2] + b0v;
                    float v3 = acc[mt][nt][3] + b1v;
                    if (GELU) { v0 = gelu_f(v0); v1 = gelu_f(v1); v2 = gelu_f(v2); v3 = gelu_f(v3); }
                    if (OM == 2) {
                        stage[nl * 132 + r0] = v0;
                        stage[(nl + 1) * 132 + r0] = v1;
                        stage[nl * 132 + r0 + 8] = v2;
                        stage[(nl + 1) * 132 + r0 + 8] = v3;
                    } else {
                        stage[r0 * 68 + nl] = v0;
                        stage[r0 * 68 + nl + 1] = v1;
                        stage[(r0 + 8) * 68 + nl] = v2;
                        stage[(r0 + 8) * 68 + nl + 1] = v3;
                    }
                }
            }
        }
        __syncthreads();
        if (OM == 2) {
            int bidx = m0 >> 12;
            int l0 = m0 & 4095;
#pragma unroll
            for (int p = 0; p < 8; p++) {
                int nl = p * 8 + warp;
                int m4 = lane * 4;
                float4 v = *(float4*)&stage[nl * 132 + m4];
                int ng = n0 + nh * 64 + nl;
                long base = ((long)((bidx << 8) + ng)) * 4096 + l0 + m4;
                __half z0 = __float2half_rn(v.x), z1 = __float2half_rn(v.y);
                __half z2 = __float2half_rn(v.z), z3 = __float2half_rn(v.w);
                uint64_t pk = (uint64_t)*(uint16_t*)&z0 | ((uint64_t)*(uint16_t*)&z1 << 16)
                            | ((uint64_t)*(uint16_t*)&z2 << 32) | ((uint64_t)*(uint16_t*)&z3 << 48);
                *(uint64_t*)&Co[base] = pk;
            }
        } else if (OM == 1) {
#pragma unroll
            for (int p = 0; p < 8; p++) {
                int idx = tid + p * 256;
                int r = idx >> 4;
                int c4 = (idx & 15) * 4;
                int n = n0 + nh * 64 + c4;
                float4 v = *(float4*)&stage[r * 68 + c4];
                long base = (long)(m0 + r) * ldc + n;
                __half z0 = __float2half_rn(v.x), z1 = __float2half_rn(v.y);
                __half z2 = __float2half_rn(v.z), z3 = __float2half_rn(v.w);
                uint64_t pk = (uint64_t)*(uint16_t*)&z0 | ((uint64_t)*(uint16_t*)&z1 << 16)
                            | ((uint64_t)*(uint16_t*)&z2 << 32) | ((uint64_t)*(uint16_t*)&z3 << 48);
                *(uint64_t*)&Co[base] = pk;
            }
        } else {
#pragma unroll
            for (int p = 0; p < 8; p++) {
                int idx = tid + p * 256;
                int r = idx >> 4;
                int c4 = (idx & 15) * 4;
                int n = n0 + nh * 64 + c4;
                if (n < Nvalid) {
                    float4 v = *(float4*)&stage[r * 68 + c4];
                    *(float4*)&Cf[(long)(m0 + r) * ldc + n] = v;
                }
            }
        }
        __syncthreads();
    }
}

// ---------------- precompute per-head matrices (fp16 hi/lo output) ----------------
__global__ void precompute_kernel(const float* __restrict__ log_dt,
                                  const float* __restrict__ log_A_real,
                                  const float* __restrict__ A_imag,
                                  const float* __restrict__ B_re,
                                  const float* __restrict__ B_im,
                                  const float* __restrict__ C_re,
                                  const float* __restrict__ C_im)
{
    int h = blockIdx.x;
    int t = threadIdx.x;   // 0..63
    __shared__ float s_dtr[NST], s_dti[NST], s_c2r[NST], s_c2i[NST];
    __shared__ float s_k[CH];

    float dt = expf(log_dt[h]);
    if (t < NST) {
        int n = t;
        float Ar = -expf(log_A_real[h * NST + n]);
        float Ai = A_imag[h * NST + n];
        float dtr = dt * Ar, dti = dt * Ai;
        float er = expf(dtr);
        float Er = er * cosf(dti) - 1.0f;
        float Ei = er * sinf(dti);
        float br = B_re[h * NST + n], bi = B_im[h * NST + n];
        float cr = C_re[h * NST + n], ci = C_im[h * NST + n];
        float BCr = br * cr - bi * ci;
        float BCi = br * ci + bi * cr;
        float numr = BCr * Er - BCi * Ei;
        float numi = BCr * Ei + BCi * Er;
        float den = Ar * Ar + Ai * Ai;
        float cpr = (numr * Ar + numi * Ai) / den;
        float cpi = (numi * Ar - numr * Ai) / den;
        s_c2r[n] = 2.0f * cpr;
        s_c2i[n] = 2.0f * cpi;
        s_dtr[n] = dtr;
        s_dti[n] = dti;
        float e64 = expf(64.0f * dtr);
        g_wS[(h * NST + n) * 2 + 0] = e64 * cosf(64.0f * dti);
        g_wS[(h * NST + n) * 2 + 1] = e64 * sinf(64.0f * dti);
    }
    __syncthreads();

    float kt = 0.0f;
    for (int n = 0; n < NST; n++) {
        float dtr = s_dtr[n], dti = s_dti[n];
        float c2r = s_c2r[n], c2i = s_c2i[n];
        float p = (float)(63 - t);
        float ep = expf(p * dtr);
        float vr = ep * cosf(p * dti), vi = ep * sinf(p * dti);
        uint16_t hh, ll;
        splith(vr, hh, ll);
        g_VSh[h * 4096 + (2 * n) * 64 + t] = hh; g_VSl[h * 4096 + (2 * n) * 64 + t] = ll;
        splith(vi, hh, ll);
        g_VSh[h * 4096 + (2 * n + 1) * 64 + t] = hh; g_VSl[h * 4096 + (2 * n + 1) * 64 + t] = ll;
        float pt = (float)t;
        float et = expf(pt * dtr);
        float wr = et * cosf(pt * dti), wi = et * sinf(pt * dti);
        kt += c2r * wr - c2i * wi;
        float p1 = (float)(t + 1);
        float e1 = expf(p1 * dtr);
        float w1r = e1 * cosf(p1 * dti), w1i = e1 * sinf(p1 * dti);
        float gr = c2r * w1r - c2i * w1i;
        float gi = -(c2r * w1i + c2i * w1r);
        splith(gr, hh, ll);
        g_CMSh[h * 8192 + t * 128 + 64 + 2 * n] = hh; g_CMSl[h * 8192 + t * 128 + 64 + 2 * n] = ll;
        splith(gi, hh, ll);
        g_CMSh[h * 8192 + t * 128 + 64 + 2 * n + 1] = hh; g_CMSl[h * 8192 + t * 128 + 64 + 2 * n + 1] = ll;
    }
    s_k[t] = kt;
    __syncthreads();
    for (int j = 0; j < CH; j++) {
        float val = (j <= t) ? s_k[t - j] : 0.0f;
        uint16_t hh, ll; splith(val, hh, ll);
        g_CMSh[h * 8192 + t * 128 + j] = hh;
        g_CMSl[h * 8192 + t * 128 + j] = ll;
    }
}

// ================= fused stageA + scan + stageC (fp16 2-term) =================
#define FU_U  0                  // u fp16 single plane, 64x72 (9216)
#define FU_W  9216               // V hi/lo (phase1) or CM hi/lo (phase3)
#define FU_VH FU_W
#define FU_VL (FU_W + 9216)
#define FU_CH FU_W
#define FU_CL (FU_W + 17408)
#define FU_E  44032              // fp32 E, stride 66 (16896)
#define FU_P  60928              // P fp16 single plane, 64x72 (9216); temps overlap
#define FU_SMEM 70144

__global__ void __launch_bounds__(256, 2) stageAC(const float* __restrict__ Dskip)
{
    extern __shared__ char sm[];
    uint16_t* sU  = (uint16_t*)(sm + FU_U);
    uint16_t* sVh = (uint16_t*)(sm + FU_VH);
    uint16_t* sVl = (uint16_t*)(sm + FU_VL);
    uint16_t* sCh = (uint16_t*)(sm + FU_CH);
    uint16_t* sCl = (uint16_t*)(sm + FU_CL);
    float*    sE  = (float*)(sm + FU_E);
    uint16_t* sP  = (uint16_t*)(sm + FU_P);
    float*    sTf   = (float*)(sm + FU_P);
    float*    sPref = (float*)(sm + FU_P + 2048);

    uint32_t pU = smem_u32(sU);
    uint32_t pVh = smem_u32(sVh), pVl = smem_u32(sVl);
    uint32_t pCh = smem_u32(sCh), pCl = smem_u32(sCl);
    uint32_t pP = smem_u32(sP);

    int bh = blockIdx.x, h = bh & (HH - 1);
    int tid = threadIdx.x, warp = tid >> 5, lane = tid & 31;
    int warp_m = warp >> 1, warp_n = warp & 1;
    int g = lane >> 2, tg = lane & 3;
    const uint16_t* uh = g_uH + (long)bh * LL;

    uint32_t a_row72 = (uint32_t)(lane & 15) * 144 + ((lane & 16) ? 16u : 0u);
    uint32_t b_row72 = ((uint32_t)(lane & 7) + ((lane & 16) ? 8u : 0u)) * 144 + ((lane & 8) ? 16u : 0u);
    uint32_t b_row136 = ((uint32_t)(lane & 7) + ((lane & 16) ? 8u : 0u)) * 272 + ((lane & 8) ? 16u : 0u);

    // ---- load u fp16 plane + V hi/lo ----
    {
        const uint16_t* vh = g_VSh + h * 4096;
        const uint16_t* vl = g_VSl + h * 4096;
#pragma unroll
        for (int p = 0; p < 2; p++) {
            int i = tid + p * 256;
            int row = i >> 3, seg = i & 7;
            *(uint4*)&sU[row * 72 + seg * 8] = *(const uint4*)&uh[row * 64 + seg * 8];
            *(uint4*)&sVh[row * 72 + seg * 8] = *(const uint4*)&vh[row * 64 + seg * 8];
            *(uint4*)&sVl[row * 72 + seg * 8] = *(const uint4*)&vl[row * 64 + seg * 8];
        }
    }
    __syncthreads();

    // ---- phase 1: E = U V^T  (2 MMA terms) ----
    {
        float acc[4][4];
#pragma unroll
        for (int nt = 0; nt < 4; nt++)
#pragma unroll
            for (int q = 0; q < 4; q++) acc[nt][q] = 0.0f;
        int ra = warp_m * 16;
#pragma unroll
        for (int ks = 0; ks < 4; ks++) {
            uint32_t kboff = (uint32_t)(ks * 16) * 2;
            uint32_t ah[4];
            ldsm_x4(ah, pU + (uint32_t)ra * 144 + a_row72 + kboff);
            uint32_t bhp[2][4], blp[2][4];
#pragma unroll
            for (int ntp = 0; ntp < 2; ntp++) {
                uint32_t nb = (uint32_t)(warp_n * 32 + ntp * 16) * 144 + b_row72 + kboff;
                ldsm_x4(bhp[ntp], pVh + nb);
                ldsm_x4(blp[ntp], pVl + nb);
            }
#pragma unroll
            for (int ntp = 0; ntp < 2; ntp++)
#pragma unroll
                for (int sub = 0; sub < 2; sub++)
                    mma16816h(acc[ntp * 2 + sub], ah, bhp[ntp][sub * 2], bhp[ntp][sub * 2 + 1]);
#pragma unroll
            for (int ntp = 0; ntp < 2; ntp++)
#pragma unroll
                for (int sub = 0; sub < 2; sub++)
                    mma16816h(acc[ntp * 2 + sub], ah, blp[ntp][sub * 2], blp[ntp][sub * 2 + 1]);
        }
        int ra2 = warp_m * 16;
#pragma unroll
        for (int nt = 0; nt < 4; nt++) {
            int s = warp_n * 32 + nt * 8 + tg * 2;
            sE[(ra2 + g) * 66 + s] = acc[nt][0];
            sE[(ra2 + g) * 66 + s + 1] = acc[nt][1];
            sE[(ra2 + g + 8) * 66 + s] = acc[nt][2];
            sE[(ra2 + g + 8) * 66 + s + 1] = acc[nt][3];
        }
    }
    __syncthreads();

    // ---- load CM hi/lo (overwrites V region) ----
    {
        const uint16_t* ch = g_CMSh + h * 8192;
        const uint16_t* cl = g_CMSl + h * 8192;
#pragma unroll
        for (int p = 0; p < 4; p++) {
            int i = tid + p * 256;
            int row = i >> 4, seg = i & 15;
            *(uint4*)&sCh[row * 136 + seg * 8] = *(const uint4*)&ch[row * 128 + seg * 8];
            *(uint4*)&sCl[row * 136 + seg * 8] = *(const uint4*)&cl[row * 128 + seg * 8];
        }
    }

    // ---- phase 2: hierarchical scan -> P fp16 plane ----
    int segi = tid >> 5;
    int n = tid & 31;
    float wr = g_wS[(h * NST + n) * 2 + 0];
    float wi = g_wS[(h * NST + n) * 2 + 1];
    {
        float sr = 0.0f, si = 0.0f;
#pragma unroll
        for (int j = 0; j < 8; j++) {
            int c = segi * 8 + j;
            float er = sE[c * 66 + 2 * n], ei = sE[c * 66 + 2 * n + 1];
            float nsr = wr * sr - wi * si + er;
            si = wr * si + wi * sr + ei;
            sr = nsr;
        }
        sTf[segi * 64 + 2 * n] = sr;
        sTf[segi * 64 + 2 * n + 1] = si;
    }
    __syncthreads();
    if (tid < 32) {
        float w2r = wr * wr - wi * wi, w2i = 2.0f * wr * wi;
        float w4r = w2r * w2r - w2i * w2i, w4i = 2.0f * w2r * w2i;
        float w8r = w4r * w4r - w4i * w4i, w8i = 2.0f * w4r * w4i;
        float pr = 0.0f, pi = 0.0f;
#pragma unroll
        for (int s = 0; s < 8; s++) {
            sPref[s * 64 + 2 * n] = pr;
            sPref[s * 64 + 2 * n + 1] = pi;
            float tr = sTf[s * 64 + 2 * n], ti = sTf[s * 64 + 2 * n + 1];
            float npr = w8r * pr - w8i * pi + tr;
            pi = w8r * pi + w8i * pr + ti;
            pr = npr;
        }
    }
    __syncthreads();
    {
        float pr = sPref[segi * 64 + 2 * n];
        float pi = sPref[segi * 64 + 2 * n + 1];
        __syncthreads();   // all prefix reads done before P writes
#pragma unroll
        for (int j = 0; j < 8; j++) {
            int c = segi * 8 + j;
            __half hr = __float2half_rn(pr);
            __half hi = __float2half_rn(pi);
            sP[c * 72 + 2 * n] = *(uint16_t*)&hr;
            sP[c * 72 + 2 * n + 1] = *(uint16_t*)&hi;
            float er = sE[c * 66 + 2 * n], ei = sE[c * 66 + 2 * n + 1];
            float npr = wr * pr - wi * pi + er;
            pi = wr * pi + wi * pr + ei;
            pr = npr;
        }
    }
    __syncthreads();

    // ---- phase 3: Y = [u|P] * CM^T + Dskip*u, gelu, +u  (2 MMA terms) ----
    {
        float acc[4][4];
#pragma unroll
        for (int nt = 0; nt < 4; nt++)
#pragma unroll
            for (int q = 0; q < 4; q++) acc[nt][q] = 0.0f;
        int ra = warp_m * 16;
#pragma unroll
        for (int ks = 0; ks < 8; ks++) {
            uint32_t aBase = (ks < 4) ? pU : pP;
            uint32_t kloc = (uint32_t)((ks & 3) * 16) * 2;
            uint32_t ah[4];
            ldsm_x4(ah, aBase + (uint32_t)ra * 144 + a_row72 + kloc);
            uint32_t kb136 = (uint32_t)(ks * 16) * 2;
            uint32_t bhp[2][4], blp[2][4];
#pragma unroll
            for (int ntp = 0; ntp < 2; ntp++) {
                uint32_t nb = (uint32_t)(warp_n * 32 + ntp * 16) * 272 + b_row136 + kb136;
                ldsm_x4(bhp[ntp], pCh + nb);
                ldsm_x4(blp[ntp], pCl + nb);
            }
#pragma unroll
            for (int ntp = 0; ntp < 2; ntp++)
#pragma unroll
                for (int sub = 0; sub < 2; sub++)
                    mma16816h(acc[ntp * 2 + sub], ah, bhp[ntp][sub * 2], bhp[ntp][sub * 2 + 1]);
#pragma unroll
            for (int ntp = 0; ntp < 2; ntp++)
#pragma unroll
                for (int sub = 0; sub < 2; sub++)
                    mma16816h(acc[ntp * 2 + sub], ah, blp[ntp][sub * 2], blp[ntp][sub * 2 + 1]);
        }

        float dsk = Dskip[h];
        uint16_t* hp = g_hresH + (long)bh * LL;
        int ra2 = warp_m * 16;
#pragma unroll
        for (int nt = 0; nt < 4; nt++) {
            int t = warp_n * 32 + nt * 8 + tg * 2;
            float u00 = __half2float(*(__half*)&sU[(ra2 + g) * 72 + t]);
            float u01 = __half2float(*(__half*)&sU[(ra2 + g) * 72 + t + 1]);
            float u10 = __half2float(*(__half*)&sU[(ra2 + g + 8) * 72 + t]);
            float u11 = __half2float(*(__half*)&sU[(ra2 + g + 8) * 72 + t + 1]);
            float y0 = gelu_f(acc[nt][0] + dsk * u00) + u00;
            float y1 = gelu_f(acc[nt][1] + dsk * u01) + u01;
            float y2 = gelu_f(acc[nt][2] + dsk * u10) + u10;
            float y3 = gelu_f(acc[nt][3] + dsk * u11) + u11;
            __half z0 = __float2half_rn(y0), z1 = __float2half_rn(y1);
            __half z2 = __float2half_rn(y2), z3 = __float2half_rn(y3);
            *(uint32_t*)&hp[(ra2 + g) * 64 + t] =
                (uint32_t)*(uint16_t*)&z0 | ((uint32_t)*(uint16_t*)&z1 << 16);
            *(uint32_t*)&hp[(ra2 + g + 8) * 64 + t] =
                (uint32_t)*(uint16_t*)&z2 | ((uint32_t)*(uint16_t*)&z3 << 16);
        }
    }
}

// ---------------- layernorm + transpose (B,H,L) -> (B,L,H), fp16 in/out ----------------
__global__ void __launch_bounds__(256, 1) layernorm_kernel(const float* __restrict__ ln_g,
                                                           const float* __restrict__ ln_b)
{
    int b = blockIdx.y;
    int l0 = blockIdx.x * 32;
    __shared__ float tile[256][33];
    int tid = threadIdx.x;
    int w = tid >> 5, lane = tid & 31;
    const uint16_t* hp = g_hresH + (long)b * HH * LL;
    for (int hh = w; hh < 256; hh += 8) {
        tile[hh][lane] = __half2float(*(const __half*)&hp[(long)hh * LL + l0 + lane]);
    }
    __syncthreads();
    uint16_t* op = g_tlnH + ((long)b * LL + l0) * HH;
#pragma unroll
    for (int q = 0; q < 4; q++) {
        int tok = w * 4 + q;
        float s = 0.0f, sq = 0.0f;
#pragma unroll
        for (int j = 0; j < 8; j++) {
            float v = tile[lane + 32 * j][tok];
            s += v;
            sq += v * v;
        }
#pragma unroll
        for (int o = 16; o > 0; o >>= 1) {
            s += __shfl_xor_sync(0xffffffffu, s, o);
            sq += __shfl_xor_sync(0xffffffffu, sq, o);
        }
        float mean = s * (1.0f / 256.0f);
        float var = sq * (1.0f / 256.0f) - mean * mean;
        float rstd = rsqrtf(var + 1e-5f);
#pragma unroll
        for (int j = 0; j < 8; j++) {
            int hh = lane + 32 * j;
            float v = (tile[hh][tok] - mean) * rstd * ln_g[hh] + ln_b[hh];
            __half hv = __float2half_rn(v);
            op[(long)tok * HH + hh] = *(uint16_t*)&hv;
        }
    }
}

// ---------------- launcher ----------------
extern "C" void kernel_launch(void* const* d_in, const int* in_sizes, int n_in,
                              void* d_out, int out_size)
{
    const float* x          = (const float*)d_in[0];
    const float* enc_w      = (const float*)d_in[1];
    const float* enc_b      = (const float*)d_in[2];
    const float* log_dt     = (const float*)d_in[3];
    const float* log_A_real = (const float*)d_in[4];
    const float* A_imag     = (const float*)d_in[5];
    const float* B_re       = (const float*)d_in[6];
    const float* B_im       = (const float*)d_in[7];
    const float* C_re       = (const float*)d_in[8];
    const float* C_im       = (const float*)d_in[9];
    const float* Dskip      = (const float*)d_in[10];
    const float* ln_g       = (const float*)d_in[11];
    const float* ln_b       = (const float*)d_in[12];
    const float* dec1_w     = (const float*)d_in[13];
    const float* dec1_b     = (const float*)d_in[14];
    const float* dec2_w     = (const float*)d_in[15];
    const float* dec2_b     = (const float*)d_in[16];
    float* out = (float*)d_out;

    void *puh = 0;
    void *pxh = 0, *pwe = 0, *pw1 = 0, *pw2 = 0, *ptl = 0, *pz = 0;
    cudaGetSymbolAddress(&puh, g_uH);
    cudaGetSymbolAddress(&pxh, g_xH);
    cudaGetSymbolAddress(&pwe, g_wencH);
    cudaGetSymbolAddress(&pw1, g_w1H);
    cudaGetSymbolAddress(&pw2, g_w2H);
    cudaGetSymbolAddress(&ptl, g_tlnH);
    cudaGetSymbolAddress(&pz, g_zH);

    cudaFuncSetAttribute(gemm_h<false, 2>, cudaFuncAttributeMaxDynamicSharedMemorySize, GH_SMEM);
    cudaFuncSetAttribute(gemm_h<true, 1>,  cudaFuncAttributeMaxDynamicSharedMemorySize, GH_SMEM);
    cudaFuncSetAttribute(gemm_h<false, 0>, cudaFuncAttributeMaxDynamicSharedMemorySize, GH_SMEM);
    cudaFuncSetAttribute(stageAC, cudaFuncAttributeMaxDynamicSharedMemorySize, FU_SMEM);

    // #1..#3 (keeps enc at launch #4 for ncu capture)
    conv_pad_h<<<(MTOK * 128 + 255) / 256, 256>>>(x, (uint16_t*)pxh, MTOK, DIN, 128, MTOK * 128);
    conv_pad_h<<<(HH * 128 + 255) / 256, 256>>>(enc_w, (uint16_t*)pwe, HH, DIN, 128, HH * 128);
    conv_pad_h<<<(DMID * HH + 255) / 256, 256>>>(dec1_w, (uint16_t*)pw1, DMID, HH, HH, DMID * HH);

    // #4: encoder GEMM -> g_uH fp16 (B,H,L)   [ncu capture target]
    gemm_h<false, 2><<<dim3(2, 512), 256, GH_SMEM>>>(
        (const uint16_t*)pxh, (const uint16_t*)pwe,
        enc_b, nullptr, (uint16_t*)puh, 128, HH, 0);

    // #5, #6
    precompute_kernel<<<HH, 64>>>(log_dt, log_A_real, A_imag, B_re, B_im, C_re, C_im);
    conv_pad_h<<<(128 * DMID + 255) / 256, 256>>>(dec2_w, (uint16_t*)pw2, DOUTP, DMID, DMID, 128 * DMID);

    // #7: fused chunk-states + scan + output stage (fp16 2-term)
    stageAC<<<BB * HH, 256, FU_SMEM>>>(Dskip);

    // #8: layernorm + transpose -> fp16 plane
    layernorm_kernel<<<dim3(LL / 32, BB), 256>>>(ln_g, ln_b);

    // #9, #10: decoder MLP (pure fp16)
    gemm_h<true, 1><<<dim3(4, 512), 256, GH_SMEM>>>(
        (const uint16_t*)ptl, (const uint16_t*)pw1,
        dec1_b, nullptr, (uint16_t*)pz, HH, DMID, DMID);

    gemm_h<false, 0><<<dim3(1, 512), 256, GH_SMEM>>>(
        (const uint16_t*)pz, (const uint16_t*)pw2,
        dec2_b, out, nullptr, DMID, DOUTP, DOUTP);
}